// round 16
// baseline (speedup 1.0000x reference)
#include <cuda_runtime.h>
#include <cuda_bf16.h>
#include <math.h>
#include <stdint.h>

#define B_   2
#define S_   2048
#define H_   1024
#define NH_  16
#define HD_  64
#define BSH  (B_*S_*H_)

typedef unsigned long long u64;

// ---------------- mma.sync helpers (sm_80+ portable tensor path) -------------
__device__ __forceinline__ uint32_t smem_to_u32(const void* p){
    uint32_t a;
    asm("{ .reg .u64 t; cvta.to.shared.u64 t, %1; cvt.u32.u64 %0, t; }" : "=r"(a) : "l"(p));
    return a;
}
__device__ __forceinline__ void ldsm_x4(uint32_t* r, uint32_t addr){
    asm volatile("ldmatrix.sync.aligned.m8n8.x4.shared.b16 {%0,%1,%2,%3}, [%4];"
        : "=r"(r[0]),"=r"(r[1]),"=r"(r[2]),"=r"(r[3]) : "r"(addr));
}
__device__ __forceinline__ void ldsm_x2(uint32_t* r, uint32_t addr){
    asm volatile("ldmatrix.sync.aligned.m8n8.x2.shared.b16 {%0,%1}, [%2];"
        : "=r"(r[0]),"=r"(r[1]) : "r"(addr));
}
__device__ __forceinline__ void mma_bf16(float* d, const uint32_t* a, const uint32_t* b){
    asm volatile("mma.sync.aligned.m16n8k16.row.col.f32.bf16.bf16.f32 "
        "{%0,%1,%2,%3}, {%4,%5,%6,%7}, {%8,%9}, {%0,%1,%2,%3};"
        : "+f"(d[0]),"+f"(d[1]),"+f"(d[2]),"+f"(d[3])
        : "r"(a[0]),"r"(a[1]),"r"(a[2]),"r"(a[3]), "r"(b[0]),"r"(b[1]));
}
__device__ __forceinline__ uint32_t packbf2(float lo, float hi){
    uint32_t r; asm("cvt.rn.bf16x2.f32 %0, %1, %2;" : "=r"(r) : "f"(hi), "f"(lo)); return r;
}
__device__ __forceinline__ float bf2lo(uint32_t p){ return __uint_as_float(p << 16); }
__device__ __forceinline__ float bf2hi(uint32_t p){ return __uint_as_float(p & 0xffff0000u); }
__device__ __forceinline__ void cp16(uint32_t dst, const void* src){
    asm volatile("cp.async.cg.shared.global [%0], [%1], 16;" :: "r"(dst), "l"(src));
}
#define CP_COMMIT() asm volatile("cp.async.commit_group;" ::: "memory")
#define CP_WAIT0()  asm volatile("cp.async.wait_group 0;" ::: "memory")

// ---------------- device scratch --------------------------------------------
__device__ __nv_bfloat16 g_Qhi[B_*NH_*S_*HD_];   // [b][h][s][d] scaled
__device__ __nv_bfloat16 g_Qlo[B_*NH_*S_*HD_];
__device__ __nv_bfloat16 g_Khi[B_*NH_*S_*HD_];
__device__ __nv_bfloat16 g_Klo[B_*NH_*S_*HD_];
__device__ __nv_bfloat16 g_VThi[B_*NH_*HD_*S_];  // [b][h][d][s]
__device__ __nv_bfloat16 g_VTlo[B_*NH_*HD_*S_];
__device__ float g_gq[B_*H_];
__device__ float g_u [B_*H_*NH_];
__device__ float g_c [B_*NH_];
__device__ double g_red[3][32];
__device__ __nv_bfloat16 g_Ahi[B_*S_*H_];
__device__ __nv_bfloat16 g_Alo[B_*S_*H_];
__device__ __nv_bfloat16 g_WThi[3*H_*H_];
__device__ __nv_bfloat16 g_WTlo[3*H_*H_];

__global__ void init_kernel() {
    int t = threadIdx.x;   // 256
    if (t < 96) ((double*)g_red)[t] = 0.0;
    for (int i=t; i<B_*H_; i+=256) g_gq[i] = 0.f;
}

// ---------------- split hs into bf16 hi/lo ----------------------------------
__global__ void split_hs_kernel(const float* __restrict__ hs)
{
    int row = blockIdx.x;
    int c = threadIdx.x * 4;
    float4 v = *(const float4*)(hs + (size_t)row*H_ + c);
    uint32_t p0 = packbf2(v.x, v.y), p1 = packbf2(v.z, v.w);
    uint32_t l0 = packbf2(v.x - bf2lo(p0), v.y - bf2hi(p0));
    uint32_t l1 = packbf2(v.z - bf2lo(p1), v.w - bf2hi(p1));
    *(uint2*)(g_Ahi + (size_t)row*H_ + c) = make_uint2(p0, p1);
    *(uint2*)(g_Alo + (size_t)row*H_ + c) = make_uint2(l0, l1);
}

// ---------------- transpose + split W into bf16 WT[n][k] hi/lo --------------
__global__ void split_wT_kernel(const float* __restrict__ Wq,
                                const float* __restrict__ Wk,
                                const float* __restrict__ Wv)
{
    __shared__ float t[64][65];
    int mode = blockIdx.z;
    const float* W = mode==0 ? Wq : (mode==1 ? Wk : Wv);
    int k0 = blockIdx.x*64, n0 = blockIdx.y*64;
    int tid = threadIdx.x;
    #pragma unroll
    for (int i=0;i<4;i++){
        int idx = tid + i*256;
        int r = idx >> 4, c4 = (idx & 15) * 4;
        float4 v = *(const float4*)(W + (size_t)(k0+r)*H_ + n0 + c4);
        t[r][c4+0]=v.x; t[r][c4+1]=v.y; t[r][c4+2]=v.z; t[r][c4+3]=v.w;
    }
    __syncthreads();
    __nv_bfloat16* oh = g_WThi + (size_t)mode*H_*H_;
    __nv_bfloat16* ol = g_WTlo + (size_t)mode*H_*H_;
    #pragma unroll
    for (int i=0;i<4;i++){
        int idx = tid + i*256;
        int r = idx >> 4, c4 = (idx & 15) * 4;
        float x0=t[c4+0][r], x1=t[c4+1][r], x2=t[c4+2][r], x3=t[c4+3][r];
        uint32_t p0 = packbf2(x0, x1), p1 = packbf2(x2, x3);
        uint32_t l0 = packbf2(x0 - bf2lo(p0), x1 - bf2hi(p0));
        uint32_t l1 = packbf2(x2 - bf2lo(p1), x3 - bf2hi(p1));
        *(uint2*)(oh + (size_t)(n0+r)*H_ + k0 + c4) = make_uint2(p0, p1);
        *(uint2*)(ol + (size_t)(n0+r)*H_ + k0 + c4) = make_uint2(l0, l1);
    }
}

// ---------------- mma.sync split-bf16 projection GEMM (cp.async pipelined) ---
#define PLD 72
#define PBUF (4*128*PLD)                 // bf16 units per buffer
#define PROJ_SMEM (2*PBUF*2)             // 147456 B

__global__ void __launch_bounds__(256,1) projmm_kernel(
    const float* __restrict__ bq, const float* __restrict__ bk,
    const float* __restrict__ bv)
{
    extern __shared__ __nv_bfloat16 sm2[];
    uint32_t ub[2] = { smem_to_u32(sm2), smem_to_u32(sm2 + PBUF) };

    int tid = threadIdx.x, wid = tid >> 5, lane = tid & 31;
    int warpM = wid & 3, warpN = wid >> 2;
    int mode = blockIdx.z, m0 = blockIdx.y*128, n0 = blockIdx.x*128;
    const __nv_bfloat16* srcs[4] = {
        g_Ahi + (size_t)m0*H_, g_Alo + (size_t)m0*H_,
        g_WThi + (size_t)mode*H_*H_ + (size_t)n0*H_,
        g_WTlo + (size_t)mode*H_*H_ + (size_t)n0*H_ };
    const float* bias = mode==0 ? bq : (mode==1 ? bk : bv);

    float acc[2][8][4];
    #pragma unroll
    for (int mi=0;mi<2;mi++)
        #pragma unroll
        for (int ni=0;ni<8;ni++)
            #pragma unroll
            for (int r=0;r<4;r++) acc[mi][ni][r] = 0.f;

    int arow = lane & 15;
    int akof = (lane & 16) ? 8 : 0;
    int brow = lane & 7;
    int bkof = (lane & 8) ? 8 : 0;

    // issue chunk 0
    #pragma unroll
    for (int i=0;i<16;i++){
        int plane = i >> 2;
        int rem = tid + (i&3)*256;
        int row = rem >> 3, c8 = (rem & 7) * 8;
        cp16(ub[0] + (uint32_t)((plane*128*PLD + row*PLD + c8)*2),
             srcs[plane] + (size_t)row*H_ + c8);
    }
    CP_COMMIT();

    for (int kc = 0; kc < 16; kc++){
        CP_WAIT0();
        __syncthreads();
        if (kc < 15){
            #pragma unroll
            for (int i=0;i<16;i++){
                int plane = i >> 2;
                int rem = tid + (i&3)*256;
                int row = rem >> 3, c8 = (rem & 7) * 8;
                cp16(ub[(kc+1)&1] + (uint32_t)((plane*128*PLD + row*PLD + c8)*2),
                     srcs[plane] + (size_t)row*H_ + (kc+1)*64 + c8);
            }
            CP_COMMIT();
        }
        uint32_t uAh = ub[kc&1];
        uint32_t uAl = uAh + 128*PLD*2;
        uint32_t uBh = uAh + 2*128*PLD*2;
        uint32_t uBl = uAh + 3*128*PLD*2;

        #pragma unroll
        for (int ks=0; ks<4; ks++){
            uint32_t ah[2][4], al[2][4], bh[8][2], bl[8][2];
            #pragma unroll
            for (int mi=0;mi<2;mi++){
                uint32_t off = (uint32_t)(((warpM*32 + mi*16 + arow)*PLD + ks*16 + akof) * 2);
                ldsm_x4(ah[mi], uAh + off);
                ldsm_x4(al[mi], uAl + off);
            }
            #pragma unroll
            for (int ni=0;ni<8;ni++){
                uint32_t off = (uint32_t)(((warpN*64 + ni*8 + brow)*PLD + ks*16 + bkof) * 2);
                ldsm_x2(bh[ni], uBh + off);
                ldsm_x2(bl[ni], uBl + off);
            }
            #pragma unroll
            for (int mi=0;mi<2;mi++)
                #pragma unroll
                for (int ni=0;ni<8;ni++){
                    mma_bf16(acc[mi][ni], ah[mi], bh[ni]);
                    mma_bf16(acc[mi][ni], ah[mi], bl[ni]);
                    mma_bf16(acc[mi][ni], al[mi], bh[ni]);
                }
        }
    }

    float bval[8][2];
    #pragma unroll
    for (int ni=0;ni<8;ni++)
        #pragma unroll
        for (int c=0;c<2;c++)
            bval[ni][c] = __ldg(bias + n0 + warpN*64 + ni*8 + (lane&3)*2 + c);

    int hh = (n0 >> 6) + warpN;
    if (mode < 2){
        float scale = (mode==0) ? 0.125f : 1.0f;
        __nv_bfloat16* dh = (mode==0) ? g_Qhi : g_Khi;
        __nv_bfloat16* dl = (mode==0) ? g_Qlo : g_Klo;
        #pragma unroll
        for (int mi=0;mi<2;mi++)
            #pragma unroll
            for (int rg=0;rg<2;rg++){
                int m = m0 + warpM*32 + mi*16 + (lane>>2) + rg*8;
                int bidx = m >> 11, s = m & 2047;
                size_t base = ((size_t)(bidx*NH_+hh)*S_ + s)*HD_;
                #pragma unroll
                for (int ni=0;ni<8;ni++){
                    float v0 = (acc[mi][ni][rg*2+0] + bval[ni][0]) * scale;
                    float v1 = (acc[mi][ni][rg*2+1] + bval[ni][1]) * scale;
                    uint32_t ph = packbf2(v0, v1);
                    uint32_t pl = packbf2(v0 - bf2lo(ph), v1 - bf2hi(ph));
                    int doff = ni*8 + (lane&3)*2;
                    *(uint32_t*)(dh + base + doff) = ph;
                    *(uint32_t*)(dl + base + doff) = pl;
                }
            }
    } else {
        #pragma unroll
        for (int mi=0;mi<2;mi++)
            #pragma unroll
            for (int rg=0;rg<2;rg++){
                int m = m0 + warpM*32 + mi*16 + (lane>>2) + rg*8;
                int bidx = m >> 11, s = m & 2047;
                size_t base = (size_t)(bidx*NH_+hh)*HD_*S_;
                #pragma unroll
                for (int ni=0;ni<8;ni++)
                    #pragma unroll
                    for (int c=0;c<2;c++){
                        int d = ni*8 + (lane&3)*2 + c;
                        float v = acc[mi][ni][rg*2+c] + bval[ni][c];
                        __nv_bfloat16 vh = __float2bfloat16_rn(v);
                        size_t vi = base + (size_t)d*S_ + s;
                        g_VThi[vi] = vh;
                        g_VTlo[vi] = __float2bfloat16_rn(v - __bfloat162float(vh));
                    }
            }
    }
}

// ---------------- governance small kernels ----------------------------------
__global__ void gq_kernel(const float* __restrict__ gov,
                          const float* __restrict__ Wgq,
                          const float* __restrict__ bgq)
{
    __shared__ float sg[128];
    int b = blockIdx.y, kz = blockIdx.z;       // 8 k-chunks of 128
    int n = blockIdx.x*256 + threadIdx.x;
    if (threadIdx.x < 128)
        sg[threadIdx.x] = gov[b*H_ + kz*128 + threadIdx.x];
    __syncthreads();
    float acc = (kz == 0) ? bgq[n] : 0.f;
    #pragma unroll 8
    for (int k=0;k<128;k++)
        acc += sg[k] * Wgq[(size_t)(kz*128+k)*H_ + n];
    atomicAdd(&g_gq[b*H_ + n], acc);
}

__global__ void u_kernel(const float* __restrict__ Wgk)
{
    int idx = blockIdx.x*256 + threadIdx.x;
    int h = idx & 15;
    int k = (idx >> 4) & 1023;
    int b = idx >> 14;
    const float* wrow = Wgk + (size_t)k*H_ + h*HD_;
    const float* gq   = g_gq + b*H_ + h*HD_;
    float acc = 0.f;
    #pragma unroll
    for (int d=0; d<HD_; d+=4){
        float4 w = *(const float4*)(wrow + d);
        float4 g = *(const float4*)(gq + d);
        acc += w.x*g.x + w.y*g.y + w.z*g.z + w.w*g.w;
    }
    g_u[idx] = acc;
}

__global__ void c_kernel(const float* __restrict__ bgk)
{
    int t = threadIdx.x;
    if (t < 32){
        int b = t >> 4, h = t & 15;
        const float* gq = g_gq + b*H_ + h*HD_;
        const float* bp = bgk + h*HD_;
        float acc = 0.f;
        #pragma unroll
        for (int d=0;d<HD_;d++) acc += bp[d]*gq[d];
        g_c[t] = acc;
    }
}

__global__ void gov_kernel(const float* __restrict__ hs)
{
    __shared__ float shs[H_];
    __shared__ float sred[4][16];
    int bs_ = blockIdx.x;
    int b = bs_ >> 11;
    int tid = threadIdx.x;   // 128
    const float* row = hs + (size_t)bs_ * H_;
    for (int i=tid; i<H_/4; i+=128)
        *(float4*)&shs[i*4] = *(const float4*)(row + i*4);
    __syncthreads();
    float acc[16];
    #pragma unroll
    for (int h=0;h<16;h++) acc[h]=0.f;
    const float* ub = g_u + b*16384;
    #pragma unroll
    for (int kk=0;kk<8;kk++){
        int k = kk*128 + tid;
        float hv = shs[k];
        const float* up = ub + k*16;
        #pragma unroll
        for (int h4=0; h4<4; h4++){
            float4 u4 = *(const float4*)(up + h4*4);
            acc[h4*4+0] += hv*u4.x;
            acc[h4*4+1] += hv*u4.y;
            acc[h4*4+2] += hv*u4.z;
            acc[h4*4+3] += hv*u4.w;
        }
    }
    #pragma unroll
    for (int h=0;h<16;h++){
        #pragma unroll
        for (int off=16; off>0; off>>=1)
            acc[h] += __shfl_xor_sync(0xffffffffu, acc[h], off);
    }
    int warp = tid>>5, lane = tid&31;
    if (lane==0){
        #pragma unroll
        for (int h=0;h<16;h++) sred[warp][h] = acc[h];
    }
    __syncthreads();
    if (tid < 16){
        float g = sred[0][tid]+sred[1][tid]+sred[2][tid]+sred[3][tid] + g_c[b*16+tid];
        float v = fabsf(g);
        #pragma unroll
        for (int off=8; off>0; off>>=1)
            v += __shfl_xor_sync(0xffffu, v, off);
        if (tid==0) atomicAdd(&g_red[1][bs_ & 31], (double)v);
    }
}

// ---------------- flash attention mma.sync (cp.async pipelined) --------------
#define KLD 72
#define VLD 136
#define FBUF (2*128*KLD + 2*64*VLD)      // bf16 units per buffer = 35840
#define FLASH_SMEM (2*FBUF*2)            // 143360 B

__global__ void __launch_bounds__(256,1) flashmma_kernel(float* __restrict__ out)
{
    extern __shared__ __nv_bfloat16 fsm[];
    uint32_t fb[2] = { smem_to_u32(fsm), smem_to_u32(fsm + FBUF) };

    int q0 = blockIdx.x * 128;
    int h  = blockIdx.y;
    int b  = blockIdx.z;
    size_t bh = (size_t)(b*NH_ + h);
    const __nv_bfloat16* Qh_ = g_Qhi + bh*S_*HD_;
    const __nv_bfloat16* Ql_ = g_Qlo + bh*S_*HD_;
    const __nv_bfloat16* ksrc[2] = { g_Khi + bh*S_*HD_, g_Klo + bh*S_*HD_ };
    const __nv_bfloat16* vsrc[2] = { g_VThi + bh*HD_*S_, g_VTlo + bh*HD_*S_ };

    int tid = threadIdx.x, wid = tid >> 5, lane = tid & 31;
    int wrow = wid * 16;
    int arow = lane & 15;
    int akof = (lane & 16) ? 8 : 0;
    int brow = lane & 7;
    int bt = (lane >> 4) & 1;
    int bk = (lane >> 3) & 1;

    // stage Q into buf0 K-planes, read fragments
    {
        __nv_bfloat16* s0 = fsm;
        #pragma unroll
        for (int i=0;i<4;i++){
            int idx = tid + i*256;
            int row = idx >> 3, c8 = (idx & 7) * 8;
            *(uint4*)(s0 + row*KLD + c8)          = *(const uint4*)(Qh_ + (size_t)(q0+row)*HD_ + c8);
            *(uint4*)(s0 + 128*KLD + row*KLD + c8) = *(const uint4*)(Ql_ + (size_t)(q0+row)*HD_ + c8);
        }
    }
    __syncthreads();
    uint32_t qh[4][4], ql[4][4];
    #pragma unroll
    for (int kt=0; kt<4; kt++){
        uint32_t off = (uint32_t)(((wrow + arow)*KLD + kt*16 + akof) * 2);
        ldsm_x4(qh[kt], fb[0] + off);
        ldsm_x4(ql[kt], fb[0] + 128*KLD*2 + off);
    }
    __syncthreads();

    // issue tile 0
    #pragma unroll
    for (int i=0;i<16;i++){
        int rem = tid + (i&3)*256;
        if (i < 8){
            int pl = i >> 2;
            int row = rem >> 3, c8 = (rem & 7) * 8;
            cp16(fb[0] + (uint32_t)((pl*128*KLD + row*KLD + c8)*2),
                 ksrc[pl] + (size_t)row*HD_ + c8);
        } else {
            int pl = (i >> 2) & 1;
            int row = rem >> 4, c8 = (rem & 15) * 8;
            cp16(fb[0] + (uint32_t)((2*128*KLD + pl*64*VLD + row*VLD + c8)*2),
                 vsrc[pl] + (size_t)row*S_ + c8);
        }
    }
    CP_COMMIT();

    float o[8][4];
    #pragma unroll
    for (int ni=0;ni<8;ni++)
        #pragma unroll
        for (int r=0;r<4;r++) o[ni][r] = 0.f;
    float m0=-1e30f, m1=-1e30f, l0=0.f, l1=0.f, t0=0.f, t1=0.f;

    for (int jt = 0; jt < 16; jt++){
        CP_WAIT0();
        __syncthreads();
        if (jt < 15){
            int j1 = (jt+1)*128;
            #pragma unroll
            for (int i=0;i<16;i++){
                int rem = tid + (i&3)*256;
                if (i < 8){
                    int pl = i >> 2;
                    int row = rem >> 3, c8 = (rem & 7) * 8;
                    cp16(fb[(jt+1)&1] + (uint32_t)((pl*128*KLD + row*KLD + c8)*2),
                         ksrc[pl] + (size_t)(j1+row)*HD_ + c8);
                } else {
                    int pl = (i >> 2) & 1;
                    int row = rem >> 4, c8 = (rem & 15) * 8;
                    cp16(fb[(jt+1)&1] + (uint32_t)((2*128*KLD + pl*64*VLD + row*VLD + c8)*2),
                         vsrc[pl] + (size_t)row*S_ + j1 + c8);
                }
            }
            CP_COMMIT();
        }
        uint32_t uKh = fb[jt&1];
        uint32_t uKl = uKh + 128*KLD*2;
        uint32_t uVh = uKh + 2*128*KLD*2;
        uint32_t uVl = uVh + 64*VLD*2;

        // S = Q K^T
        float sc[16][4];
        #pragma unroll
        for (int t=0;t<16;t++)
            #pragma unroll
            for (int r=0;r<4;r++) sc[t][r] = 0.f;
        #pragma unroll
        for (int ks=0; ks<4; ks++){
            #pragma unroll
            for (int p=0;p<8;p++){
                uint32_t kh4[4], kl4[4];
                uint32_t off = (uint32_t)(((p*16 + bt*8 + brow)*KLD + ks*16 + bk*8) * 2);
                ldsm_x4(kh4, uKh + off);
                ldsm_x4(kl4, uKl + off);
                mma_bf16(sc[2*p],   qh[ks], &kh4[0]);
                mma_bf16(sc[2*p],   qh[ks], &kl4[0]);
                mma_bf16(sc[2*p],   ql[ks], &kh4[0]);
                mma_bf16(sc[2*p+1], qh[ks], &kh4[2]);
                mma_bf16(sc[2*p+1], qh[ks], &kl4[2]);
                mma_bf16(sc[2*p+1], ql[ks], &kh4[2]);
            }
        }

        // online softmax
        float mx0 = -1e30f, mx1 = -1e30f;
        #pragma unroll
        for (int t=0;t<16;t++){
            mx0 = fmaxf(mx0, fmaxf(sc[t][0], sc[t][1]));
            mx1 = fmaxf(mx1, fmaxf(sc[t][2], sc[t][3]));
        }
        #pragma unroll
        for (int off=1; off<4; off<<=1){
            mx0 = fmaxf(mx0, __shfl_xor_sync(0xffffffffu, mx0, off));
            mx1 = fmaxf(mx1, __shfl_xor_sync(0xffffffffu, mx1, off));
        }
        float mn0 = fmaxf(m0, mx0), mn1 = fmaxf(m1, mx1);
        float la0=0.f, ta0=0.f, la1=0.f, ta1=0.f;
        #pragma unroll
        for (int t=0;t<16;t++){
            float s0 = sc[t][0], s1 = sc[t][1], s2 = sc[t][2], s3 = sc[t][3];
            float e0 = __expf(s0-mn0), e1 = __expf(s1-mn0);
            float e2 = __expf(s2-mn1), e3 = __expf(s3-mn1);
            la0 += e0+e1; ta0 += e0*s0 + e1*s1;
            la1 += e2+e3; ta1 += e2*s2 + e3*s3;
            sc[t][0]=e0; sc[t][1]=e1; sc[t][2]=e2; sc[t][3]=e3;
        }
        #pragma unroll
        for (int off=1; off<4; off<<=1){
            la0 += __shfl_xor_sync(0xffffffffu, la0, off);
            ta0 += __shfl_xor_sync(0xffffffffu, ta0, off);
            la1 += __shfl_xor_sync(0xffffffffu, la1, off);
            ta1 += __shfl_xor_sync(0xffffffffu, ta1, off);
        }
        float scl0 = __expf(m0-mn0), scl1 = __expf(m1-mn1);
        l0 = l0*scl0 + la0; t0 = t0*scl0 + ta0; m0 = mn0;
        l1 = l1*scl1 + la1; t1 = t1*scl1 + ta1; m1 = mn1;
        #pragma unroll
        for (int ni=0;ni<8;ni++){
            o[ni][0]*=scl0; o[ni][1]*=scl0; o[ni][2]*=scl1; o[ni][3]*=scl1;
        }

        // O += P V
        #pragma unroll
        for (int kt=0; kt<8; kt++){
            uint32_t pa[4], pb[4];
            #pragma unroll
            for (int q=0;q<4;q++){
                int t = 2*kt + (q>>1);
                float x = sc[t][(q&1)*2+0], y = sc[t][(q&1)*2+1];
                uint32_t ph = packbf2(x, y);
                pa[q] = ph;
                pb[q] = packbf2(x - bf2lo(ph), y - bf2hi(ph));
            }
            uint32_t ah4[4] = {pa[0], pa[1], pa[2], pa[3]};
            uint32_t al4[4] = {pb[0], pb[1], pb[2], pb[3]};
            #pragma unroll
            for (int p=0;p<4;p++){
                uint32_t vh4[4], vl4[4];
                uint32_t off = (uint32_t)(((p*16 + bt*8 + brow)*VLD + kt*16 + bk*8) * 2);
                ldsm_x4(vh4, uVh + off);
                ldsm_x4(vl4, uVl + off);
                mma_bf16(o[2*p],   ah4, &vh4[0]);
                mma_bf16(o[2*p],   ah4, &vl4[0]);
                mma_bf16(o[2*p],   al4, &vh4[0]);
                mma_bf16(o[2*p+1], ah4, &vh4[2]);
                mma_bf16(o[2*p+1], ah4, &vl4[2]);
                mma_bf16(o[2*p+1], al4, &vh4[2]);
            }
        }
    }

    // epilogue
    int r0 = q0 + wrow + (lane>>2), r1 = r0 + 8;
    float inv0 = 1.0f/l0, inv1 = 1.0f/l1;
    #pragma unroll
    for (int ni=0;ni<8;ni++){
        int d = ni*8 + (lane&3)*2;
        float2 w0 = make_float2(o[ni][0]*inv0, o[ni][1]*inv0);
        float2 w1 = make_float2(o[ni][2]*inv1, o[ni][3]*inv1);
        *(float2*)(out + ((size_t)b*S_ + r0)*H_ + h*HD_ + d) = w0;
        *(float2*)(out + ((size_t)b*S_ + r1)*H_ + h*HD_ + d) = w1;
    }
    if ((lane & 3) == 0){
        double es = (double)(m0 + logf(l0) - t0/l0 - 2.048e-5f)
                  + (double)(m1 + logf(l1) - t1/l1 - 2.048e-5f);
        double cs = (double)inv0 + (double)inv1;
        atomicAdd(&g_red[0][tid & 31], es);
        atomicAdd(&g_red[2][tid & 31], cs);
    }
}

__global__ void fin_kernel(float* __restrict__ out, int out_size)
{
    int t = threadIdx.x;  // 32
    double e = g_red[0][t], f = g_red[1][t], c = g_red[2][t];
    #pragma unroll
    for (int off=16; off>0; off>>=1){
        e += __shfl_xor_sync(0xffffffffu, e, off);
        f += __shfl_xor_sync(0xffffffffu, f, off);
        c += __shfl_xor_sync(0xffffffffu, c, off);
    }
    if (t == 0 && out_size >= BSH + 3){
        out[BSH+0] = (float)(e / 65536.0);
        out[BSH+1] = (float)(f / 65536.0);
        out[BSH+2] = (float)(c / 65536.0);
    }
}

extern "C" void kernel_launch(void* const* d_in, const int* in_sizes, int n_in,
                              void* d_out, int out_size) {
    const float* hs   = (const float*)d_in[0];
    const float* gov  = (const float*)d_in[1];
    const float* Wq   = (const float*)d_in[2];
    const float* bq   = (const float*)d_in[3];
    const float* Wk   = (const float*)d_in[4];
    const float* bk   = (const float*)d_in[5];
    const float* Wv   = (const float*)d_in[6];
    const float* bv   = (const float*)d_in[7];
    const float* Wgq  = (const float*)d_in[8];
    const float* bgq  = (const float*)d_in[9];
    const float* Wgk  = (const float*)d_in[10];
    const float* bgk  = (const float*)d_in[11];
    float* out = (float*)d_out;

    init_kernel<<<1, 256>>>();
    split_hs_kernel<<<B_*S_, 256>>>(hs);
    split_wT_kernel<<<dim3(16, 16, 3), 256>>>(Wq, Wk, Wv);
    cudaFuncSetAttribute(projmm_kernel, cudaFuncAttributeMaxDynamicSharedMemorySize, PROJ_SMEM);
    projmm_kernel<<<dim3(H_/128, B_*S_/128, 3), 256, PROJ_SMEM>>>(bq, bk, bv);
    gq_kernel<<<dim3(H_/256, B_, 8), 256>>>(gov, Wgq, bgq);
    u_kernel<<<(B_*H_*NH_)/256, 256>>>(Wgk);
    c_kernel<<<1, 32>>>(bgk);
    gov_kernel<<<B_*S_, 128>>>(hs);
    cudaFuncSetAttribute(flashmma_kernel, cudaFuncAttributeMaxDynamicSharedMemorySize, FLASH_SMEM);
    flashmma_kernel<<<dim3(S_/128, NH_, B_), 256, FLASH_SMEM>>>(out);
    fin_kernel<<<1, 32>>>(out, out_size);
}